// round 6
// baseline (speedup 1.0000x reference)
#include <cuda_runtime.h>
#include <cuda_fp16.h>
#include <math.h>

// Problem constants (ManifoldGPRFilter: N=100000, D=64, E=1000000, L=10)
#define NMAX 100000
#define EMAX 1000000
#define DIM  64
#define EPSV 1e-8f

// ---------------- static device scratch (no runtime allocation) ----------------
__device__ __half2 g_Xh[(size_t)NMAX * (DIM / 2)];
__device__ __half2 g_H0[(size_t)NMAX * (DIM / 2)];
__device__ __half2 g_H1[(size_t)NMAX * (DIM / 2)];
__device__ int   g_deg[NMAX];
__device__ int   g_off[NMAX + 1];
__device__ int   g_cur[NMAX];
__device__ int2  g_edge[EMAX];     // packed (src, float-bits of val)

// decoupled-lookback scan state (reset every replay by k_prep)
#define SCAN_B 1024
#define MAXBLK 128
__device__ int g_agg[MAXBLK];
__device__ volatile int g_flag[MAXBLK];

// ---------------- prep: zero state, X -> fp16, Z = w0 * X ----------------
__global__ void k_prep(const float* __restrict__ X, __half2* __restrict__ Xh,
                       float* __restrict__ Z, const float* __restrict__ w,
                       int n, int n4) {
    int i = blockIdx.x * blockDim.x + threadIdx.x;
    if (i < n4) {
        float w0 = __ldg(w);
        float4 x = ((const float4*)X)[i];
        Xh[i * 2]     = __floats2half2_rn(x.x, x.y);
        Xh[i * 2 + 1] = __floats2half2_rn(x.z, x.w);
        float4 z;
        z.x = w0 * x.x; z.y = w0 * x.y; z.z = w0 * x.z; z.w = w0 * x.w;
        ((float4*)Z)[i] = z;
    }
    if (i < n) g_deg[i] = 0;
    if (i < MAXBLK) { g_agg[i] = 0; g_flag[i] = 0; }
}

__global__ void k_hist(const int* __restrict__ dst, int e) {
    int i = blockIdx.x * blockDim.x + threadIdx.x;
    if (i < e) atomicAdd(&g_deg[dst[i]], 1);
}

// ---------------- single-kernel exclusive scan (decoupled lookback) ----------------
// nb <= 98 blocks, all co-resident on 148 SMs -> sequential spin is deadlock-free.
__global__ void k_scan(int n, int nb) {
    __shared__ int sh[SCAN_B];
    __shared__ int s_prefix;
    int bid = blockIdx.x;
    int i = bid * SCAN_B + threadIdx.x;
    int v = (i < n) ? g_deg[i] : 0;
    sh[threadIdx.x] = v;
    __syncthreads();
    for (int o = 1; o < SCAN_B; o <<= 1) {
        int t = 0;
        if (threadIdx.x >= o) t = sh[threadIdx.x - o];
        __syncthreads();
        if (threadIdx.x >= o) sh[threadIdx.x] += t;
        __syncthreads();
    }
    if (threadIdx.x == SCAN_B - 1) {
        g_agg[bid] = sh[SCAN_B - 1];
        __threadfence();
        g_flag[bid] = 1;
    }
    if (threadIdx.x == 0) {
        int sum = 0;
        for (int b = 0; b < bid; b++) {
            while (g_flag[b] == 0) { }
            sum += g_agg[b];
        }
        s_prefix = sum;
    }
    __syncthreads();
    int pre = s_prefix;
    if (i < n) {
        int excl = pre + sh[threadIdx.x] - v;
        g_off[i] = excl;
        g_cur[i] = excl;
    }
    if (bid == nb - 1 && threadIdx.x == SCAN_B - 1)
        g_off[n] = pre + sh[SCAN_B - 1];
}

__global__ void k_scatter(const int* __restrict__ src, const int* __restrict__ dst,
                          const float* __restrict__ val, int e) {
    int i = blockIdx.x * blockDim.x + threadIdx.x;
    if (i < e) {
        int d = dst[i];
        int pos = atomicAdd(&g_cur[d], 1);
        g_edge[pos] = make_int2(src[i], __float_as_int(val[i]));
    }
}

// ---------------- fused SpMM + hyperbolic renorm + Z accumulation ----------------
// One warp per destination row. Edges in PAIRS (lanes 0-15 even edge, 16-31 odd).
// Per 16-edge block: 8 predicated edge LDGs issued together, then 8 predicated
// gathers issued together -> MLP ~8, two latency exposures per row.
#define MAXP 8
__global__ __launch_bounds__(256)
void k_spmm_renorm(const __half2* __restrict__ Hin, __half2* __restrict__ Hout,
                   float* __restrict__ Z, const float* __restrict__ w,
                   int l, int n, int writeH) {
    int warp = (blockIdx.x * blockDim.x + threadIdx.x) >> 5;
    int lane = threadIdx.x & 31;
    if (warp >= n) return;

    int half = lane >> 4;
    int sub  = lane & 15;

    int beg = __ldg(&g_off[warp]);
    int end = __ldg(&g_off[warp + 1]);

    const uint2* Hrows = reinterpret_cast<const uint2*>(Hin);
    float4 acc = make_float4(0.f, 0.f, 0.f, 0.f);

    for (int base = beg; base < end; base += 2 * MAXP) {
        int2  ed[MAXP];
        uint2 hh[MAXP];
        // batch 1: all edge records (independent, predicated)
        #pragma unroll
        for (int k = 0; k < MAXP; k++) {
            int idx = base + 2 * k + half;
            if (idx < end) ed[k] = __ldg(&g_edge[idx]);
            else           ed[k] = make_int2(0, 0);
        }
        // batch 2: all gathers (independent, predicated)
        #pragma unroll
        for (int k = 0; k < MAXP; k++) {
            int idx = base + 2 * k + half;
            if (idx < end) hh[k] = __ldg(Hrows + (size_t)ed[k].x * 16 + sub);
            else           hh[k] = make_uint2(0u, 0u);
        }
        // accumulate (val = 0 for predicated-off slots -> safe)
        #pragma unroll
        for (int k = 0; k < MAXP; k++) {
            float v = __int_as_float(ed[k].y);
            float2 a01 = __half22float2(*(const __half2*)&hh[k].x);
            float2 a23 = __half22float2(*(const __half2*)&hh[k].y);
            acc.x += v * a01.x;
            acc.y += v * a01.y;
            acc.z += v * a23.x;
            acc.w += v * a23.y;
        }
    }

    // merge parity halves
    acc.x += __shfl_down_sync(0xffffffffu, acc.x, 16);
    acc.y += __shfl_down_sync(0xffffffffu, acc.y, 16);
    acc.z += __shfl_down_sync(0xffffffffu, acc.z, 16);
    acc.w += __shfl_down_sync(0xffffffffu, acc.w, 16);

    float ss = acc.x * acc.x + acc.y * acc.y + acc.z * acc.z + acc.w * acc.w;
    #pragma unroll
    for (int o = 8; o; o >>= 1) ss += __shfl_xor_sync(0xffffffffu, ss, o);

    if (half == 0) {
        float nrm   = sqrtf(ss) + EPSV;
        float scale = tanhf(nrm) / nrm;
        float wl    = __ldg(w + l);

        float h0 = acc.x * scale;
        float h1 = acc.y * scale;
        float h2 = acc.z * scale;
        float h3 = acc.w * scale;

        if (writeH) {
            uint2 hv;
            __half2 p01 = __floats2half2_rn(h0, h1);
            __half2 p23 = __floats2half2_rn(h2, h3);
            hv.x = *(const unsigned*)&p01;
            hv.y = *(const unsigned*)&p23;
            reinterpret_cast<uint2*>(Hout)[(size_t)warp * 16 + sub] = hv;
        }

        float4* zp = reinterpret_cast<float4*>(Z + (size_t)warp * DIM) + sub;
        float4 z = *zp;
        z.x += wl * h0;
        z.y += wl * h1;
        z.z += wl * h2;
        z.w += wl * h3;
        *zp = z;
    }
}

// ---------------- launch ----------------
extern "C" void kernel_launch(void* const* d_in, const int* in_sizes, int n_in,
                              void* d_out, int out_size) {
    const float* X    = (const float*)d_in[0];
    const float* vals = (const float*)d_in[1];
    const float* w    = (const float*)d_in[2];
    const int*   src  = (const int*)d_in[3];
    const int*   dst  = (const int*)d_in[4];
    float* Z = (float*)d_out;

    int n = in_sizes[0] / DIM;
    int e = in_sizes[1];
    int L = in_sizes[2] - 1;

    __half2* xh; __half2* h0; __half2* h1;
    cudaGetSymbolAddress((void**)&xh, g_Xh);
    cudaGetSymbolAddress((void**)&h0, g_H0);
    cudaGetSymbolAddress((void**)&h1, g_H1);

    int n4 = n * DIM / 4;
    int nb = (n + SCAN_B - 1) / SCAN_B;

    // ---- prep: zero state, X->fp16, Z = w0*X ----
    k_prep<<<(n4 + 255) / 256, 256>>>(X, xh, Z, w, n, n4);
    // ---- CSR build ----
    k_hist<<<(e + 255) / 256, 256>>>(dst, e);
    k_scan<<<nb, SCAN_B>>>(n, nb);
    k_scatter<<<(e + 255) / 256, 256>>>(src, dst, vals, e);

    // ---- L propagation steps (ping-pong fp16 H buffers, fused Z) ----
    int blocks = (n * 32 + 255) / 256;
    for (int l = 1; l <= L; l++) {
        const __half2* Hin = (l == 1) ? xh : ((l & 1) ? h1 : h0);
        __half2* Hout      = ((l & 1) ? h0 : h1);
        int writeH = (l < L) ? 1 : 0;
        k_spmm_renorm<<<blocks, 256>>>(Hin, Hout, Z, w, l, n, writeH);
    }
}

// round 7
// speedup vs baseline: 1.1643x; 1.1643x over previous
#include <cuda_runtime.h>
#include <cuda_fp16.h>
#include <math.h>

// Problem constants (ManifoldGPRFilter: N=100000, D=64, E=1000000, L=10)
#define NMAX 100000
#define EMAX 1000000
#define DIM  64
#define EPSV 1e-8f

// ---------------- static device scratch (no runtime allocation) ----------------
__device__ __half2 g_Xh[(size_t)NMAX * (DIM / 2)];
__device__ __half2 g_H0[(size_t)NMAX * (DIM / 2)];
__device__ __half2 g_H1[(size_t)NMAX * (DIM / 2)];
__device__ int   g_deg[NMAX];
__device__ int   g_off[NMAX + 1];
__device__ int   g_cur[NMAX];
__device__ int2  g_edge[EMAX];     // packed (src, float-bits of val)

// decoupled-lookback scan state (reset every replay by k_prep)
#define SCAN_B 1024
#define MAXBLK 128
__device__ int g_agg[MAXBLK];
__device__ volatile int g_flag[MAXBLK];

// ---------------- prep: zero state, X -> fp16, Z = w0 * X ----------------
__global__ void k_prep(const float* __restrict__ X, __half2* __restrict__ Xh,
                       float* __restrict__ Z, const float* __restrict__ w,
                       int n, int n4) {
    int i = blockIdx.x * blockDim.x + threadIdx.x;
    if (i < n4) {
        float w0 = __ldg(w);
        float4 x = ((const float4*)X)[i];
        Xh[i * 2]     = __floats2half2_rn(x.x, x.y);
        Xh[i * 2 + 1] = __floats2half2_rn(x.z, x.w);
        float4 z;
        z.x = w0 * x.x; z.y = w0 * x.y; z.z = w0 * x.z; z.w = w0 * x.w;
        ((float4*)Z)[i] = z;
    }
    if (i < n) g_deg[i] = 0;
    if (i < MAXBLK) { g_agg[i] = 0; g_flag[i] = 0; }
}

__global__ void k_hist(const int* __restrict__ dst, int e) {
    int i = blockIdx.x * blockDim.x + threadIdx.x;
    if (i < e) atomicAdd(&g_deg[dst[i]], 1);
}

// ---------------- single-kernel exclusive scan (decoupled lookback) ----------------
// nb <= 98 blocks, all co-resident on 148 SMs -> sequential spin is deadlock-free.
__global__ void k_scan(int n, int nb) {
    __shared__ int sh[SCAN_B];
    __shared__ int s_prefix;
    int bid = blockIdx.x;
    int i = bid * SCAN_B + threadIdx.x;
    int v = (i < n) ? g_deg[i] : 0;
    sh[threadIdx.x] = v;
    __syncthreads();
    for (int o = 1; o < SCAN_B; o <<= 1) {
        int t = 0;
        if (threadIdx.x >= o) t = sh[threadIdx.x - o];
        __syncthreads();
        if (threadIdx.x >= o) sh[threadIdx.x] += t;
        __syncthreads();
    }
    if (threadIdx.x == SCAN_B - 1) {
        g_agg[bid] = sh[SCAN_B - 1];
        __threadfence();
        g_flag[bid] = 1;
    }
    if (threadIdx.x == 0) {
        int sum = 0;
        for (int b = 0; b < bid; b++) {
            while (g_flag[b] == 0) { }
            sum += g_agg[b];
        }
        s_prefix = sum;
    }
    __syncthreads();
    int pre = s_prefix;
    if (i < n) {
        int excl = pre + sh[threadIdx.x] - v;
        g_off[i] = excl;
        g_cur[i] = excl;
    }
    if (bid == nb - 1 && threadIdx.x == SCAN_B - 1)
        g_off[n] = pre + sh[SCAN_B - 1];
}

__global__ void k_scatter(const int* __restrict__ src, const int* __restrict__ dst,
                          const float* __restrict__ val, int e) {
    int i = blockIdx.x * blockDim.x + threadIdx.x;
    if (i < e) {
        int d = dst[i];
        int pos = atomicAdd(&g_cur[d], 1);
        g_edge[pos] = make_int2(src[i], __float_as_int(val[i]));
    }
}

// ---------------- fused SpMM + hyperbolic renorm + Z accumulation ----------------
// One warp per destination row, edges in PAIRS:
//   lanes 0-15 gather edge e's 128B row; lanes 16-31 edge e+1's row.
// Register-tight + __launch_bounds__(256, 8) => 64 warps/SM.
__global__ __launch_bounds__(256, 8)
void k_spmm_renorm(const __half2* __restrict__ Hin, __half2* __restrict__ Hout,
                   float* __restrict__ Z, const float* __restrict__ w,
                   int l, int n, int writeH) {
    int warp = (blockIdx.x * blockDim.x + threadIdx.x) >> 5;
    int lane = threadIdx.x & 31;
    if (warp >= n) return;

    int half = lane >> 4;
    int sub  = lane & 15;

    int beg = __ldg(&g_off[warp]);
    int end = __ldg(&g_off[warp + 1]);

    const uint2* Hrows = reinterpret_cast<const uint2*>(Hin) + sub;
    const int2*  ep    = g_edge + half;

    float4 acc = make_float4(0.f, 0.f, 0.f, 0.f);

    int e = beg;
    for (; e + 4 <= end; e += 4) {
        int2 ed0 = __ldg(ep + e);
        int2 ed1 = __ldg(ep + e + 2);
        uint2 h0 = __ldg(Hrows + (size_t)ed0.x * 16);
        uint2 h1 = __ldg(Hrows + (size_t)ed1.x * 16);
        float v0 = __int_as_float(ed0.y);
        float v1 = __int_as_float(ed1.y);
        float2 a01 = __half22float2(*(const __half2*)&h0.x);
        float2 a23 = __half22float2(*(const __half2*)&h0.y);
        float2 b01 = __half22float2(*(const __half2*)&h1.x);
        float2 b23 = __half22float2(*(const __half2*)&h1.y);
        acc.x += v0 * a01.x + v1 * b01.x;
        acc.y += v0 * a01.y + v1 * b01.y;
        acc.z += v0 * a23.x + v1 * b23.x;
        acc.w += v0 * a23.y + v1 * b23.y;
    }
    if (e + 2 <= end) {
        int2 ed = __ldg(ep + e);
        uint2 h = __ldg(Hrows + (size_t)ed.x * 16);
        float v = __int_as_float(ed.y);
        float2 a01 = __half22float2(*(const __half2*)&h.x);
        float2 a23 = __half22float2(*(const __half2*)&h.y);
        acc.x += v * a01.x;
        acc.y += v * a01.y;
        acc.z += v * a23.x;
        acc.w += v * a23.y;
        e += 2;
    }
    if (e < end && half == 0) {
        int2 ed = __ldg(&g_edge[e]);
        uint2 h = __ldg(Hrows + (size_t)ed.x * 16);
        float v = __int_as_float(ed.y);
        float2 a01 = __half22float2(*(const __half2*)&h.x);
        float2 a23 = __half22float2(*(const __half2*)&h.y);
        acc.x += v * a01.x;
        acc.y += v * a01.y;
        acc.z += v * a23.x;
        acc.w += v * a23.y;
    }

    // merge parity halves
    acc.x += __shfl_down_sync(0xffffffffu, acc.x, 16);
    acc.y += __shfl_down_sync(0xffffffffu, acc.y, 16);
    acc.z += __shfl_down_sync(0xffffffffu, acc.z, 16);
    acc.w += __shfl_down_sync(0xffffffffu, acc.w, 16);

    float ss = acc.x * acc.x + acc.y * acc.y + acc.z * acc.z + acc.w * acc.w;
    #pragma unroll
    for (int o = 8; o; o >>= 1) ss += __shfl_xor_sync(0xffffffffu, ss, o);

    if (half == 0) {
        float nrm   = sqrtf(ss) + EPSV;
        float scale = tanhf(nrm) / nrm;
        float wl    = __ldg(w + l);

        float h0 = acc.x * scale;
        float h1 = acc.y * scale;
        float h2 = acc.z * scale;
        float h3 = acc.w * scale;

        if (writeH) {
            uint2 hv;
            __half2 p01 = __floats2half2_rn(h0, h1);
            __half2 p23 = __floats2half2_rn(h2, h3);
            hv.x = *(const unsigned*)&p01;
            hv.y = *(const unsigned*)&p23;
            reinterpret_cast<uint2*>(Hout)[(size_t)warp * 16 + sub] = hv;
        }

        float4* zp = reinterpret_cast<float4*>(Z + (size_t)warp * DIM) + sub;
        float4 z = *zp;
        z.x += wl * h0;
        z.y += wl * h1;
        z.z += wl * h2;
        z.w += wl * h3;
        *zp = z;
    }
}

// ---------------- launch ----------------
extern "C" void kernel_launch(void* const* d_in, const int* in_sizes, int n_in,
                              void* d_out, int out_size) {
    const float* X    = (const float*)d_in[0];
    const float* vals = (const float*)d_in[1];
    const float* w    = (const float*)d_in[2];
    const int*   src  = (const int*)d_in[3];
    const int*   dst  = (const int*)d_in[4];
    float* Z = (float*)d_out;

    int n = in_sizes[0] / DIM;
    int e = in_sizes[1];
    int L = in_sizes[2] - 1;

    __half2* xh; __half2* h0; __half2* h1;
    cudaGetSymbolAddress((void**)&xh, g_Xh);
    cudaGetSymbolAddress((void**)&h0, g_H0);
    cudaGetSymbolAddress((void**)&h1, g_H1);

    int n4 = n * DIM / 4;
    int nb = (n + SCAN_B - 1) / SCAN_B;

    // ---- prep: zero state, X->fp16, Z = w0*X ----
    k_prep<<<(n4 + 255) / 256, 256>>>(X, xh, Z, w, n, n4);
    // ---- CSR build ----
    k_hist<<<(e + 255) / 256, 256>>>(dst, e);
    k_scan<<<nb, SCAN_B>>>(n, nb);
    k_scatter<<<(e + 255) / 256, 256>>>(src, dst, vals, e);

    // ---- L propagation steps (ping-pong fp16 H buffers, fused Z) ----
    int blocks = (n * 32 + 255) / 256;
    for (int l = 1; l <= L; l++) {
        const __half2* Hin = (l == 1) ? xh : ((l & 1) ? h1 : h0);
        __half2* Hout      = ((l & 1) ? h0 : h1);
        int writeH = (l < L) ? 1 : 0;
        k_spmm_renorm<<<blocks, 256>>>(Hin, Hout, Z, w, l, n, writeH);
    }
}

// round 8
// speedup vs baseline: 1.1886x; 1.0208x over previous
#include <cuda_runtime.h>
#include <cuda_fp16.h>
#include <math.h>

// Problem constants (ManifoldGPRFilter: N=100000, D=64, E=1000000, L=10)
#define NMAX 100000
#define EMAX 1000000
#define DIM  64
#define EPSV 1e-8f

// ---------------- static device scratch (no runtime allocation) ----------------
__device__ __half2 g_Xh[(size_t)NMAX * (DIM / 2)];
__device__ __half2 g_H0[(size_t)NMAX * (DIM / 2)];
__device__ __half2 g_H1[(size_t)NMAX * (DIM / 2)];
__device__ int   g_deg[NMAX];
__device__ int   g_off[NMAX + 1];
__device__ int   g_cur[NMAX];
__device__ int2  g_edge[EMAX];     // packed (src, float-bits of val)

// decoupled-lookback scan state (reset every replay by k_prep)
#define SCAN_B 1024
#define MAXBLK 128
__device__ int g_agg[MAXBLK];
__device__ volatile int g_flag[MAXBLK];

// ---------------- prep: zero state, X -> fp16, Z = w0*X, degree histogram ----------------
// Launch order note: this is launch #1; scan #2; scatter #3; first SpMM #4
// (the profiler consistently captures the 4th launch).
__global__ void k_prep(const float* __restrict__ X, __half2* __restrict__ Xh,
                       float* __restrict__ Z, const float* __restrict__ w,
                       const int* __restrict__ dst,
                       int n, int n4, int e) {
    int i = blockIdx.x * blockDim.x + threadIdx.x;
    if (i < n) g_deg[i] = 0;
    if (i < MAXBLK) { g_agg[i] = 0; g_flag[i] = 0; }
    if (i < n4) {
        float w0 = __ldg(w);
        float4 x = ((const float4*)X)[i];
        Xh[i * 2]     = __floats2half2_rn(x.x, x.y);
        Xh[i * 2 + 1] = __floats2half2_rn(x.z, x.w);
        float4 z;
        z.x = w0 * x.x; z.y = w0 * x.y; z.z = w0 * x.z; z.w = w0 * x.w;
        ((float4*)Z)[i] = z;
    }
    // grid-wide barrier-free histogram: wait until all zeroing by THIS thread's
    // block cannot race — zeroing of g_deg happens in the same kernel, so we must
    // order zero -> atomicAdd across blocks. Use a separate pass trick: since
    // g_deg is zeroed by threads with i<n and the histogram reads dst[i<e] with
    // arbitrary targets, do the histogram in a SECOND grid-stride sweep guarded
    // by cooperative-free ordering: instead, zero using the PREVIOUS replay's
    // guarantee is unsafe. Simplest safe approach: histogram moved to k_scan's
    // first phase is also racy. => Do histogram here but zero g_deg at the END
    // of the previous replay is not allowed (determinism). Resolution: histogram
    // uses a dedicated accumulation pass in this kernel via grid-stride AFTER a
    // device-scope fence loop is NOT possible without cooperative launch.
    //
    // SAFE DESIGN ACTUALLY USED: g_deg zeroing and histogram are done with
    // atomicExch/atomicAdd on DISJOINT arrays: histogram accumulates into g_cur
    // (zeroed here), and k_scan reads g_cur as the degree source.
    if (i < n) g_cur[i] = 0;
    __threadfence();
}

// histogram into g_cur (separate launch to preserve ordering; cheap)
__global__ void k_hist(const int* __restrict__ dst, int e) {
    int i = blockIdx.x * blockDim.x + threadIdx.x;
    if (i < e) atomicAdd(&g_cur[dst[i]], 1);
}

// ---------------- single-kernel exclusive scan (decoupled lookback) ----------------
// Reads degrees from g_cur, writes offsets to g_off and resets g_cur to the
// running cursor for the scatter.
__global__ void k_scan(int n, int nb) {
    __shared__ int sh[SCAN_B];
    __shared__ int s_prefix;
    int bid = blockIdx.x;
    int i = bid * SCAN_B + threadIdx.x;
    int v = (i < n) ? g_cur[i] : 0;
    sh[threadIdx.x] = v;
    __syncthreads();
    for (int o = 1; o < SCAN_B; o <<= 1) {
        int t = 0;
        if (threadIdx.x >= o) t = sh[threadIdx.x - o];
        __syncthreads();
        if (threadIdx.x >= o) sh[threadIdx.x] += t;
        __syncthreads();
    }
    if (threadIdx.x == SCAN_B - 1) {
        g_agg[bid] = sh[SCAN_B - 1];
        __threadfence();
        g_flag[bid] = 1;
    }
    if (threadIdx.x == 0) {
        int sum = 0;
        for (int b = 0; b < bid; b++) {
            while (g_flag[b] == 0) { }
            sum += g_agg[b];
        }
        s_prefix = sum;
    }
    __syncthreads();
    int pre = s_prefix;
    if (i < n) {
        int excl = pre + sh[threadIdx.x] - v;
        g_off[i] = excl;
        g_cur[i] = excl;
    }
    if (bid == nb - 1 && threadIdx.x == SCAN_B - 1)
        g_off[n] = pre + sh[SCAN_B - 1];
}

__global__ void k_scatter(const int* __restrict__ src, const int* __restrict__ dst,
                          const float* __restrict__ val, int e) {
    int i = blockIdx.x * blockDim.x + threadIdx.x;
    if (i < e) {
        int d = dst[i];
        int pos = atomicAdd(&g_cur[d], 1);
        g_edge[pos] = make_int2(src[i], __float_as_int(val[i]));
    }
}

// ---------------- fused SpMM + hyperbolic renorm + Z accumulation ----------------
// One warp per destination row, edges in PAIRS:
//   lanes 0-15 gather edge e's 128B row; lanes 16-31 edge e+1's row.
// Block = 128 threads (4 warps): lower max-degree residency inflation per block.
__global__ __launch_bounds__(128)
void k_spmm_renorm(const __half2* __restrict__ Hin, __half2* __restrict__ Hout,
                   float* __restrict__ Z, const float* __restrict__ w,
                   int l, int n, int writeH) {
    int warp = (blockIdx.x * blockDim.x + threadIdx.x) >> 5;
    int lane = threadIdx.x & 31;
    if (warp >= n) return;

    int half = lane >> 4;
    int sub  = lane & 15;

    int beg = __ldg(&g_off[warp]);
    int end = __ldg(&g_off[warp + 1]);

    const uint2* Hrows = reinterpret_cast<const uint2*>(Hin);
    float4 acc = make_float4(0.f, 0.f, 0.f, 0.f);

    int e = beg;
    for (; e + 4 <= end; e += 4) {
        int2 ed0 = __ldg(&g_edge[e + half]);
        int2 ed1 = __ldg(&g_edge[e + 2 + half]);
        uint2 h0 = __ldg(Hrows + (size_t)ed0.x * 16 + sub);
        uint2 h1 = __ldg(Hrows + (size_t)ed1.x * 16 + sub);
        float v0 = __int_as_float(ed0.y);
        float v1 = __int_as_float(ed1.y);
        float2 a01 = __half22float2(*(const __half2*)&h0.x);
        float2 a23 = __half22float2(*(const __half2*)&h0.y);
        float2 b01 = __half22float2(*(const __half2*)&h1.x);
        float2 b23 = __half22float2(*(const __half2*)&h1.y);
        acc.x += v0 * a01.x + v1 * b01.x;
        acc.y += v0 * a01.y + v1 * b01.y;
        acc.z += v0 * a23.x + v1 * b23.x;
        acc.w += v0 * a23.y + v1 * b23.y;
    }
    if (e + 2 <= end) {
        int2 ed = __ldg(&g_edge[e + half]);
        uint2 h = __ldg(Hrows + (size_t)ed.x * 16 + sub);
        float v = __int_as_float(ed.y);
        float2 a01 = __half22float2(*(const __half2*)&h.x);
        float2 a23 = __half22float2(*(const __half2*)&h.y);
        acc.x += v * a01.x;
        acc.y += v * a01.y;
        acc.z += v * a23.x;
        acc.w += v * a23.y;
        e += 2;
    }
    if (e < end && half == 0) {
        int2 ed = __ldg(&g_edge[e]);
        uint2 h = __ldg(Hrows + (size_t)ed.x * 16 + sub);
        float v = __int_as_float(ed.y);
        float2 a01 = __half22float2(*(const __half2*)&h.x);
        float2 a23 = __half22float2(*(const __half2*)&h.y);
        acc.x += v * a01.x;
        acc.y += v * a01.y;
        acc.z += v * a23.x;
        acc.w += v * a23.y;
    }

    // merge parity halves
    acc.x += __shfl_down_sync(0xffffffffu, acc.x, 16);
    acc.y += __shfl_down_sync(0xffffffffu, acc.y, 16);
    acc.z += __shfl_down_sync(0xffffffffu, acc.z, 16);
    acc.w += __shfl_down_sync(0xffffffffu, acc.w, 16);

    float ss = acc.x * acc.x + acc.y * acc.y + acc.z * acc.z + acc.w * acc.w;
    #pragma unroll
    for (int o = 8; o; o >>= 1) ss += __shfl_xor_sync(0xffffffffu, ss, o);

    if (half == 0) {
        float nrm   = sqrtf(ss) + EPSV;
        float scale = tanhf(nrm) / nrm;
        float wl    = __ldg(w + l);

        float h0 = acc.x * scale;
        float h1 = acc.y * scale;
        float h2 = acc.z * scale;
        float h3 = acc.w * scale;

        if (writeH) {
            uint2 hv;
            __half2 p01 = __floats2half2_rn(h0, h1);
            __half2 p23 = __floats2half2_rn(h2, h3);
            hv.x = *(const unsigned*)&p01;
            hv.y = *(const unsigned*)&p23;
            reinterpret_cast<uint2*>(Hout)[(size_t)warp * 16 + sub] = hv;
        }

        float4* zp = reinterpret_cast<float4*>(Z + (size_t)warp * DIM) + sub;
        float4 z = *zp;
        z.x += wl * h0;
        z.y += wl * h1;
        z.z += wl * h2;
        z.w += wl * h3;
        *zp = z;
    }
}

// ---------------- launch ----------------
extern "C" void kernel_launch(void* const* d_in, const int* in_sizes, int n_in,
                              void* d_out, int out_size) {
    const float* X    = (const float*)d_in[0];
    const float* vals = (const float*)d_in[1];
    const float* w    = (const float*)d_in[2];
    const int*   src  = (const int*)d_in[3];
    const int*   dst  = (const int*)d_in[4];
    float* Z = (float*)d_out;

    int n = in_sizes[0] / DIM;
    int e = in_sizes[1];
    int L = in_sizes[2] - 1;

    __half2* xh; __half2* h0; __half2* h1;
    cudaGetSymbolAddress((void**)&xh, g_Xh);
    cudaGetSymbolAddress((void**)&h0, g_H0);
    cudaGetSymbolAddress((void**)&h1, g_H1);

    int n4 = n * DIM / 4;
    int nb = (n + SCAN_B - 1) / SCAN_B;

    // ---- prep: zero state, X->fp16, Z = w0*X ----
    k_prep<<<(n4 + 255) / 256, 256>>>(X, xh, Z, w, dst, n, n4, e);
    // ---- CSR build ----
    k_hist<<<(e + 255) / 256, 256>>>(dst, e);
    k_scan<<<nb, SCAN_B>>>(n, nb);
    k_scatter<<<(e + 255) / 256, 256>>>(src, dst, vals, e);

    // ---- L propagation steps (ping-pong fp16 H buffers, fused Z) ----
    int blocks = (n * 32 + 127) / 128;
    for (int l = 1; l <= L; l++) {
        const __half2* Hin = (l == 1) ? xh : ((l & 1) ? h1 : h0);
        __half2* Hout      = ((l & 1) ? h0 : h1);
        int writeH = (l < L) ? 1 : 0;
        k_spmm_renorm<<<blocks, 128>>>(Hin, Hout, Z, w, l, n, writeH);
    }
}